// round 14
// baseline (speedup 1.0000x reference)
#include <cuda_runtime.h>
#include <cuda_fp8.h>
#include <cuda_bf16.h>
#include <cstdint>

// ============================================================================
// y[b,s,o] = 4 * sum_i e4m3(x[b,s,i]*0.5) * W_e4m3[o,i]  + bias[o]
// M = 16384, N = 4096, K = 4096, fp32 out.
// R14: R13 with ONE barrier per chunk:
//   chunk top = wait<0> -> sync -> prefetch -> commit.
//   At the wait, pending = {G(ck), G(ck+1)} (G(ck+2) not yet committed), so
//   wait<0> is ~free; the single sync gives global visibility of G(ck+1)
//   (enables the cross-chunk ks0 preload) AND fences the stage overwrite.
// ============================================================================

#define DI __device__ __forceinline__

// ---------------- device scratch (bytes; bf16 payload) ----------------------
__device__ uint8_t g_Aq[16384u * 4096u * 2u];   // 128MB activations bf16
__device__ uint8_t g_Wq[4096u * 4096u * 2u];    // 32MB weights bf16
__device__ int     g_wflag;                     // 1 if weight buffer is fp32

// ---------------- helpers ---------------------------------------------------
DI uint32_t smem_u32(const void* p) {
    uint32_t a;
    asm("{ .reg .u64 t; cvta.to.shared.u64 t, %1; cvt.u32.u64 %0, t; }"
        : "=r"(a) : "l"(p));
    return a;
}
DI void cp_async16(uint32_t dst, const void* src) {
    asm volatile("cp.async.cg.shared.global [%0], [%1], 16;" :: "r"(dst), "l"(src));
}
DI void cp_commit() { asm volatile("cp.async.commit_group;" ::: "memory"); }
template <int N> DI void cp_wait() {
    asm volatile("cp.async.wait_group %0;" :: "n"(N) : "memory");
}
DI void ldmatrix4(uint32_t& r0, uint32_t& r1, uint32_t& r2, uint32_t& r3, uint32_t a) {
    asm volatile("ldmatrix.sync.aligned.m8n8.x4.shared.b16 {%0,%1,%2,%3}, [%4];"
                 : "=r"(r0), "=r"(r1), "=r"(r2), "=r"(r3) : "r"(a));
}
DI void mma_bf16(float& c0, float& c1, float& c2, float& c3,
                 uint32_t a0, uint32_t a1, uint32_t a2, uint32_t a3,
                 uint32_t b0, uint32_t b1) {
    asm volatile(
        "mma.sync.aligned.m16n8k16.row.col.f32.bf16.bf16.f32 "
        "{%0,%1,%2,%3}, {%4,%5,%6,%7}, {%8,%9}, {%0,%1,%2,%3};"
        : "+f"(c0), "+f"(c1), "+f"(c2), "+f"(c3)
        : "r"(a0), "r"(a1), "r"(a2), "r"(a3), "r"(b0), "r"(b1));
}

// e4m3 quantize (x*0.5, satfinite) then EXACT widen to bf16
DI __nv_bfloat16 qdq_bf16(float x) {
    __nv_fp8_storage_t q = __nv_cvt_float_to_fp8(x * 0.5f, __NV_SATFINITE, __NV_E4M3);
    float f = __half2float(__nv_cvt_fp8_to_halfraw(q, __NV_E4M3));   // exact
    return __float2bfloat16(f);
}
DI __nv_bfloat16 e4m3_bf16(uint8_t b) {
    float f = __half2float(__nv_cvt_fp8_to_halfraw((__nv_fp8_storage_t)b, __NV_E4M3));
    return __float2bfloat16(f);
}

// ============================================================================
// Kernel 1: quantize activations -> bf16(e4m3(x*0.5))
// ============================================================================
__global__ void quant_act(const float4* __restrict__ in, int n4) {
    uint2* out = reinterpret_cast<uint2*>(g_Aq);
    int i = blockIdx.x * blockDim.x + threadIdx.x;
    int stride = gridDim.x * blockDim.x;
    for (; i < n4; i += stride) {
        float4 v = in[i];
        __nv_bfloat162 p0 = __nv_bfloat162(qdq_bf16(v.x), qdq_bf16(v.y));
        __nv_bfloat162 p1 = __nv_bfloat162(qdq_bf16(v.z), qdq_bf16(v.w));
        uint2 o;
        o.x = *reinterpret_cast<uint32_t*>(&p0);
        o.y = *reinterpret_cast<uint32_t*>(&p1);
        out[i] = o;
    }
}

// ============================================================================
// Kernel 2: weight dtype detect + normalize to bf16
// ============================================================================
__global__ void detect_wdtype(const float* __restrict__ w) {
    if (blockIdx.x == 0 && threadIdx.x == 0) {
        int ok = 1;
        for (int i = 0; i < 256; i++) {
            float x = w[i];
            if (!(fabsf(x) <= 448.0f)) { ok = 0; break; }
        }
        g_wflag = ok;
    }
}

__global__ void prep_w(const void* __restrict__ w, int n) {
    int flag = g_wflag;
    int idx = blockIdx.x * blockDim.x + threadIdx.x;
    int stride = gridDim.x * blockDim.x;
    __nv_bfloat16* o = reinterpret_cast<__nv_bfloat16*>(g_Wq);
    if (flag) {
        const float4* wf = (const float4*)w;
        for (int i = idx; i < n / 4; i += stride) {
            float4 v = wf[i];
            o[i * 4 + 0] = e4m3_bf16(__nv_cvt_float_to_fp8(v.x, __NV_SATFINITE, __NV_E4M3));
            o[i * 4 + 1] = e4m3_bf16(__nv_cvt_float_to_fp8(v.y, __NV_SATFINITE, __NV_E4M3));
            o[i * 4 + 2] = e4m3_bf16(__nv_cvt_float_to_fp8(v.z, __NV_SATFINITE, __NV_E4M3));
            o[i * 4 + 3] = e4m3_bf16(__nv_cvt_float_to_fp8(v.w, __NV_SATFINITE, __NV_E4M3));
        }
    } else {
        const uchar4* wb = (const uchar4*)w;
        for (int i = idx; i < n / 4; i += stride) {
            uchar4 v = wb[i];
            o[i * 4 + 0] = e4m3_bf16(v.x);
            o[i * 4 + 1] = e4m3_bf16(v.y);
            o[i * 4 + 2] = e4m3_bf16(v.z);
            o[i * 4 + 3] = e4m3_bf16(v.w);
        }
    }
}

// ============================================================================
// Kernel 3: BF16 GEMM (native HMMA)
// ============================================================================
#define BM 128
#define BN 128
#define KBYTES 8192                  // row stride (4096 bf16)
#define BKB 128                      // chunk bytes per row = 64 bf16
#define NDIM 4096
#define MDIM 16384
#define KCHUNKS 64
#define STAGES 3
#define NTHREADS 256

#define A_BYTES (BM * 128)           // 16384
#define B_BYTES (BN * 128)           // 16384
#define STAGE_BYTES (A_BYTES + B_BYTES)   // 32768
#define SM_TOTAL (STAGES * STAGE_BYTES)   // 98304 per CTA

// thread loads 4 A rows + 4 B rows (rows stride 32 -> swizzled unit constant)
DI void load_stage(uint32_t As, uint32_t Bs,
                   const uint8_t* __restrict__ ag,
                   const uint8_t* __restrict__ bg) {
#pragma unroll
    for (int i = 0; i < BM / 32; i++)
        cp_async16(As + i * (32 * 128), ag + (size_t)i * (32 * KBYTES));
#pragma unroll
    for (int i = 0; i < BN / 32; i++)
        cp_async16(Bs + i * (32 * 128), bg + (size_t)i * (32 * KBYTES));
}

__global__ void __launch_bounds__(NTHREADS, 2)
gemm_kernel(const float* __restrict__ bias, float* __restrict__ out) {
    extern __shared__ char smem[];
    uint32_t sb = smem_u32(smem);
    int tid = (int)threadIdx.x;
    int wid = tid >> 5;
    int lid = tid & 31;
    int wm = wid & 1;                 // M dir: 2 warps * 64 rows
    int wn = wid >> 1;                // N dir: 4 warps * 32 cols
    int tm = blockIdx.y;
    int tn = blockIdx.x;

    // ---- per-thread constant load addressing ----
    int lcol = tid & 7;
    int lrow = tid >> 3;              // 0..31
    uint32_t aSmBase = (uint32_t)(lrow * 128 + ((lcol ^ (lrow & 7)) << 4));
    uint32_t bSmBase = aSmBase + A_BYTES;
    const uint8_t* ag = g_Aq + ((size_t)(tm * BM + lrow)) * KBYTES + lcol * 16;
    const uint8_t* bg = g_Wq + ((size_t)(tn * BN + lrow)) * KBYTES + lcol * 16;

    float acc[4][4][4];
#pragma unroll
    for (int mi = 0; mi < 4; mi++)
#pragma unroll
        for (int ni = 0; ni < 4; ni++)
#pragma unroll
            for (int r = 0; r < 4; r++) acc[mi][ni][r] = 0.0f;

    // lane-derived ldmatrix source coordinates (proven R2-R13)
    int a_row_l = (lid & 7) + ((lid >> 3) & 1) * 8;
    int a_half  = lid >> 4;
    int b_row_l = (lid & 7) + ((lid >> 4) & 1) * 8;
    int b_half  = (lid >> 3) & 1;

    uint32_t aOff[4], bOff[2];
#pragma unroll
    for (int mi = 0; mi < 4; mi++) {
        int row = wm * 64 + mi * 16 + a_row_l;
        aOff[mi] = (uint32_t)(row * 128 + ((a_half ^ (row & 7)) << 4));
    }
#pragma unroll
    for (int np = 0; np < 2; np++) {
        int n = wn * 32 + np * 16 + b_row_l;
        bOff[np] = (uint32_t)(n * 128 + ((b_half ^ (n & 7)) << 4)) + A_BYTES;
    }

    // prefetch bias into registers (epilogue needs 8 values per thread)
    int qrow = lid >> 2;
    int qcol = (lid & 3) * 2;
    int n0 = tn * BN + wn * 32 + qcol;
    float bias0[4], bias1[4];
#pragma unroll
    for (int ni = 0; ni < 4; ni++) {
        bias0[ni] = __ldg(bias + n0 + ni * 8);
        bias1[ni] = __ldg(bias + n0 + ni * 8 + 1);
    }

    // prologue: fill stages 0,1 (chunks 0,1)
#pragma unroll
    for (int s = 0; s < STAGES - 1; s++) {
        load_stage(sb + s * STAGE_BYTES + aSmBase, sb + s * STAGE_BYTES + bSmBase,
                   ag, bg);
        cp_commit();
        ag += BKB;
        bg += BKB;
    }

    uint32_t a[2][4][4];
    uint32_t b[2][4][2];
    int cs = 0;                        // compute stage (chunk ck)
    int ps = STAGES - 1;               // produce stage (chunk ck+2)
    bool primed = false;

    for (int ck = 0; ck < KCHUNKS; ck++) {
        // ---- chunk top: wait<0> -> sync -> prefetch -> commit ----
        // Pending here = {G(ck), G(ck+1)} (G(ck+2) committed below), so
        // wait<0> is ~free; sync then gives: (a) global visibility of
        // G(ck+1) for the ks3 preload, (b) stage-overwrite fence for ps.
        cp_wait<0>();
        __syncthreads();
        if (ck + STAGES - 1 < KCHUNKS) {
            load_stage(sb + ps * STAGE_BYTES + aSmBase,
                       sb + ps * STAGE_BYTES + bSmBase, ag, bg);
            ag += BKB;
            bg += BKB;
            cp_commit();
        }
        if (++ps == STAGES) ps = 0;

        uint32_t As = sb + cs * STAGE_BYTES;
        int cs1 = cs + 1; if (cs1 == STAGES) cs1 = 0;
        uint32_t AsNext = sb + cs1 * STAGE_BYTES;   // globally resident
        cs = cs1;

        if (!primed) {                 // first chunk only: serial ks0 preload
#pragma unroll
            for (int mi = 0; mi < 4; mi++)
                ldmatrix4(a[0][mi][0], a[0][mi][1], a[0][mi][2], a[0][mi][3],
                          As + aOff[mi]);
#pragma unroll
            for (int np = 0; np < 2; np++)
                ldmatrix4(b[0][2 * np][0], b[0][2 * np][1],
                          b[0][2 * np + 1][0], b[0][2 * np + 1][1],
                          As + bOff[np]);
            primed = true;
        }

#pragma unroll
        for (int ks = 0; ks < 4; ks++) {
            int cur = ks & 1;
            int nxt = cur ^ 1;
            if (ks < 3) {
                uint32_t x = (uint32_t)((ks + 1) << 5);
#pragma unroll
                for (int mi = 0; mi < 4; mi++)
                    ldmatrix4(a[nxt][mi][0], a[nxt][mi][1], a[nxt][mi][2], a[nxt][mi][3],
                              (As + aOff[mi]) ^ x);
#pragma unroll
                for (int np = 0; np < 2; np++)
                    ldmatrix4(b[nxt][2 * np][0], b[nxt][2 * np][1],
                              b[nxt][2 * np + 1][0], b[nxt][2 * np + 1][1],
                              (As + bOff[np]) ^ x);
            } else if (ck + 1 < KCHUNKS) {
                // preload NEXT chunk's ks0 (stage cs1; safe per sync)
#pragma unroll
                for (int mi = 0; mi < 4; mi++)
                    ldmatrix4(a[nxt][mi][0], a[nxt][mi][1], a[nxt][mi][2], a[nxt][mi][3],
                              AsNext + aOff[mi]);
#pragma unroll
                for (int np = 0; np < 2; np++)
                    ldmatrix4(b[nxt][2 * np][0], b[nxt][2 * np][1],
                              b[nxt][2 * np + 1][0], b[nxt][2 * np + 1][1],
                              AsNext + bOff[np]);
            }
#pragma unroll
            for (int mi = 0; mi < 4; mi++)
#pragma unroll
                for (int ni = 0; ni < 4; ni++)
                    mma_bf16(acc[mi][ni][0], acc[mi][ni][1], acc[mi][ni][2], acc[mi][ni][3],
                             a[cur][mi][0], a[cur][mi][1], a[cur][mi][2], a[cur][mi][3],
                             b[cur][ni][0], b[cur][ni][1]);
        }
    }

    // Epilogue: out = acc*4 + bias (bias pre-loaded)
    int m0 = tm * BM + wm * 64 + qrow;
#pragma unroll
    for (int mi = 0; mi < 4; mi++) {
#pragma unroll
        for (int ni = 0; ni < 4; ni++) {
            int n = n0 + ni * 8;
            int mA = m0 + mi * 16;
            int mB = mA + 8;
            float2 v0 = make_float2(acc[mi][ni][0] * 4.0f + bias0[ni],
                                    acc[mi][ni][1] * 4.0f + bias1[ni]);
            float2 v1 = make_float2(acc[mi][ni][2] * 4.0f + bias0[ni],
                                    acc[mi][ni][3] * 4.0f + bias1[ni]);
            *reinterpret_cast<float2*>(out + (size_t)mA * NDIM + n) = v0;
            *reinterpret_cast<float2*>(out + (size_t)mB * NDIM + n) = v1;
        }
    }
}

// ============================================================================
// Host launch
// ============================================================================
extern "C" void kernel_launch(void* const* d_in, const int* in_sizes, int n_in,
                              void* d_out, int out_size) {
    const float* input = nullptr;
    const void*  weight = nullptr;
    const float* bias = nullptr;
    for (int i = 0; i < n_in; i++) {
        if (in_sizes[i] == 4 * 4096 * 4096)  input = (const float*)d_in[i];
        else if (in_sizes[i] == 4096 * 4096) weight = d_in[i];
        else if (in_sizes[i] == 4096)        bias = (const float*)d_in[i];
    }
    if (!input)  input  = (const float*)d_in[0];
    if (!weight) weight = d_in[1];
    if (!bias)   bias   = (const float*)d_in[2];
    float* out = (float*)d_out;

    int n4 = (4 * 4096 * 4096) / 4;
    quant_act<<<8192, 256>>>((const float4*)input, n4);

    detect_wdtype<<<1, 1>>>((const float*)weight);
    prep_w<<<2048, 256>>>(weight, 4096 * 4096);

    static bool attr_set = false;
    if (!attr_set) {
        cudaFuncSetAttribute(gemm_kernel,
                             cudaFuncAttributeMaxDynamicSharedMemorySize, SM_TOTAL);
        attr_set = true;
    }
    dim3 grid(NDIM / BN, MDIM / BM);   // (32, 128)
    gemm_kernel<<<grid, NTHREADS, SM_TOTAL>>>(bias, out);
}

// round 15
// speedup vs baseline: 1.0487x; 1.0487x over previous
#include <cuda_runtime.h>
#include <cuda_fp8.h>
#include <cuda_bf16.h>
#include <cstdint>

// ============================================================================
// y[b,s,o] = 4 * sum_i e4m3(x[b,s,i]*0.5) * W_e4m3[o,i]  + bias[o]
// M = 16384, N = 4096, K = 4096, fp32 out.
// R15: 64x64 warp tiles (4 warps / 128 thr per CTA, 2 CTAs/SM) to cut smem
//   fragment duplication A:4x->2x (crossbar was the binder at 89%).
//   R13 pipeline semantics (sync1->prefetch->commit->wait<1>->sync2 +
//   cross-chunk ks0 preload). detect folded into prep_w.
// ============================================================================

#define DI __device__ __forceinline__

// ---------------- device scratch (bytes; bf16 payload) ----------------------
__device__ uint8_t g_Aq[16384u * 4096u * 2u];   // 128MB activations bf16
__device__ uint8_t g_Wq[4096u * 4096u * 2u];    // 32MB weights bf16

// ---------------- helpers ---------------------------------------------------
DI uint32_t smem_u32(const void* p) {
    uint32_t a;
    asm("{ .reg .u64 t; cvta.to.shared.u64 t, %1; cvt.u32.u64 %0, t; }"
        : "=r"(a) : "l"(p));
    return a;
}
DI void cp_async16(uint32_t dst, const void* src) {
    asm volatile("cp.async.cg.shared.global [%0], [%1], 16;" :: "r"(dst), "l"(src));
}
DI void cp_commit() { asm volatile("cp.async.commit_group;" ::: "memory"); }
template <int N> DI void cp_wait() {
    asm volatile("cp.async.wait_group %0;" :: "n"(N) : "memory");
}
DI void ldmatrix4(uint32_t& r0, uint32_t& r1, uint32_t& r2, uint32_t& r3, uint32_t a) {
    asm volatile("ldmatrix.sync.aligned.m8n8.x4.shared.b16 {%0,%1,%2,%3}, [%4];"
                 : "=r"(r0), "=r"(r1), "=r"(r2), "=r"(r3) : "r"(a));
}
DI void mma_bf16(float& c0, float& c1, float& c2, float& c3,
                 uint32_t a0, uint32_t a1, uint32_t a2, uint32_t a3,
                 uint32_t b0, uint32_t b1) {
    asm volatile(
        "mma.sync.aligned.m16n8k16.row.col.f32.bf16.bf16.f32 "
        "{%0,%1,%2,%3}, {%4,%5,%6,%7}, {%8,%9}, {%0,%1,%2,%3};"
        : "+f"(c0), "+f"(c1), "+f"(c2), "+f"(c3)
        : "r"(a0), "r"(a1), "r"(a2), "r"(a3), "r"(b0), "r"(b1));
}

// e4m3 quantize (x*0.5, satfinite) then EXACT widen to bf16
DI __nv_bfloat16 qdq_bf16(float x) {
    __nv_fp8_storage_t q = __nv_cvt_float_to_fp8(x * 0.5f, __NV_SATFINITE, __NV_E4M3);
    float f = __half2float(__nv_cvt_fp8_to_halfraw(q, __NV_E4M3));
    return __float2bfloat16(f);
}
DI __nv_bfloat16 e4m3_bf16(uint8_t b) {
    float f = __half2float(__nv_cvt_fp8_to_halfraw((__nv_fp8_storage_t)b, __NV_E4M3));
    return __float2bfloat16(f);
}

// ============================================================================
// Kernel 1: quantize activations -> bf16(e4m3(x*0.5))
// ============================================================================
__global__ void quant_act(const float4* __restrict__ in, int n4) {
    uint2* out = reinterpret_cast<uint2*>(g_Aq);
    int i = blockIdx.x * blockDim.x + threadIdx.x;
    int stride = gridDim.x * blockDim.x;
    for (; i < n4; i += stride) {
        float4 v = in[i];
        __nv_bfloat162 p0 = __nv_bfloat162(qdq_bf16(v.x), qdq_bf16(v.y));
        __nv_bfloat162 p1 = __nv_bfloat162(qdq_bf16(v.z), qdq_bf16(v.w));
        uint2 o;
        o.x = *reinterpret_cast<uint32_t*>(&p0);
        o.y = *reinterpret_cast<uint32_t*>(&p1);
        out[i] = o;
    }
}

// ============================================================================
// Kernel 2: weight prep with INLINE dtype detection (per-block, redundant,
// reads the same first 256 floats -> L2-cached, ~free; kills the serial
// single-thread detect kernel).
// ============================================================================
__global__ void prep_w(const void* __restrict__ w, int n) {
    const float* wf32 = (const float*)w;
    int t = threadIdx.x;                       // 256 threads
    int pred = (t < 256) ? (fabsf(wf32[t]) <= 448.0f ? 1 : 0) : 1;
    int cnt = __syncthreads_count(pred);
    int flag = (cnt == (int)blockDim.x);       // all finite & small => fp32

    int idx = blockIdx.x * blockDim.x + t;
    int stride = gridDim.x * blockDim.x;
    __nv_bfloat16* o = reinterpret_cast<__nv_bfloat16*>(g_Wq);
    if (flag) {
        const float4* wf = (const float4*)w;
        for (int i = idx; i < n / 4; i += stride) {
            float4 v = wf[i];
            o[i * 4 + 0] = e4m3_bf16(__nv_cvt_float_to_fp8(v.x, __NV_SATFINITE, __NV_E4M3));
            o[i * 4 + 1] = e4m3_bf16(__nv_cvt_float_to_fp8(v.y, __NV_SATFINITE, __NV_E4M3));
            o[i * 4 + 2] = e4m3_bf16(__nv_cvt_float_to_fp8(v.z, __NV_SATFINITE, __NV_E4M3));
            o[i * 4 + 3] = e4m3_bf16(__nv_cvt_float_to_fp8(v.w, __NV_SATFINITE, __NV_E4M3));
        }
    } else {
        const uchar4* wb = (const uchar4*)w;
        for (int i = idx; i < n / 4; i += stride) {
            uchar4 v = wb[i];
            o[i * 4 + 0] = e4m3_bf16(v.x);
            o[i * 4 + 1] = e4m3_bf16(v.y);
            o[i * 4 + 2] = e4m3_bf16(v.z);
            o[i * 4 + 3] = e4m3_bf16(v.w);
        }
    }
}

// ============================================================================
// Kernel 3: BF16 GEMM (native HMMA), 64x64 warp tiles
// ============================================================================
#define BM 128
#define BN 128
#define KBYTES 8192                  // row stride (4096 bf16)
#define BKB 128                      // chunk bytes per row = 64 bf16
#define NDIM 4096
#define MDIM 16384
#define KCHUNKS 64
#define STAGES 3
#define NTHREADS 128

#define A_BYTES (BM * 128)           // 16384
#define B_BYTES (BN * 128)           // 16384
#define STAGE_BYTES (A_BYTES + B_BYTES)   // 32768
#define SM_TOTAL (STAGES * STAGE_BYTES)   // 98304 per CTA

// 128 threads: thread loads 8 A rows + 8 B rows (row stride 16 -> swizzled
// 16B unit is per-thread constant since 16 % 8 == 0).
DI void load_stage(uint32_t As, uint32_t Bs,
                   const uint8_t* __restrict__ ag,
                   const uint8_t* __restrict__ bg) {
#pragma unroll
    for (int i = 0; i < BM / 16; i++)
        cp_async16(As + i * (16 * 128), ag + (size_t)i * (16 * KBYTES));
#pragma unroll
    for (int i = 0; i < BN / 16; i++)
        cp_async16(Bs + i * (16 * 128), bg + (size_t)i * (16 * KBYTES));
}

__global__ void __launch_bounds__(NTHREADS, 2)
gemm_kernel(const float* __restrict__ bias, float* __restrict__ out) {
    extern __shared__ char smem[];
    uint32_t sb = smem_u32(smem);
    int tid = (int)threadIdx.x;
    int wid = tid >> 5;
    int lid = tid & 31;
    int wm = wid & 1;                 // M dir: 2 warps * 64 rows
    int wn = wid >> 1;                // N dir: 2 warps * 64 cols
    int tm = blockIdx.y;
    int tn = blockIdx.x;

    // ---- per-thread constant load addressing ----
    int lcol = tid & 7;
    int lrow = tid >> 3;              // 0..15
    uint32_t aSmBase = (uint32_t)(lrow * 128 + ((lcol ^ (lrow & 7)) << 4));
    uint32_t bSmBase = aSmBase + A_BYTES;
    const uint8_t* ag = g_Aq + ((size_t)(tm * BM + lrow)) * KBYTES + lcol * 16;
    const uint8_t* bg = g_Wq + ((size_t)(tn * BN + lrow)) * KBYTES + lcol * 16;

    float acc[4][8][4];
#pragma unroll
    for (int mi = 0; mi < 4; mi++)
#pragma unroll
        for (int ni = 0; ni < 8; ni++)
#pragma unroll
            for (int r = 0; r < 4; r++) acc[mi][ni][r] = 0.0f;

    // lane-derived ldmatrix source coordinates (proven R2-R14)
    int a_row_l = (lid & 7) + ((lid >> 3) & 1) * 8;
    int a_half  = lid >> 4;
    int b_row_l = (lid & 7) + ((lid >> 4) & 1) * 8;
    int b_half  = (lid >> 3) & 1;

    uint32_t aOff[4], bOff[4];
#pragma unroll
    for (int mi = 0; mi < 4; mi++) {
        int row = wm * 64 + mi * 16 + a_row_l;
        aOff[mi] = (uint32_t)(row * 128 + ((a_half ^ (row & 7)) << 4));
    }
#pragma unroll
    for (int np = 0; np < 4; np++) {
        int n = wn * 64 + np * 16 + b_row_l;
        bOff[np] = (uint32_t)(n * 128 + ((b_half ^ (n & 7)) << 4)) + A_BYTES;
    }

    // prologue: fill stages 0,1 (chunks 0,1)
#pragma unroll
    for (int s = 0; s < STAGES - 1; s++) {
        load_stage(sb + s * STAGE_BYTES + aSmBase, sb + s * STAGE_BYTES + bSmBase,
                   ag, bg);
        cp_commit();
        ag += BKB;
        bg += BKB;
    }

    uint32_t a[2][4][4];
    uint32_t b[2][8][2];
    int cs = 0;                        // compute stage
    int ps = STAGES - 1;               // produce stage
    bool primed = false;

    for (int ck = 0; ck < KCHUNKS; ck++) {
        // ---- R13 chunk top: sync1 -> prefetch -> commit -> wait<1> -> sync2
        __syncthreads();               // 1: all reads of stage ps done
        if (ck + STAGES - 1 < KCHUNKS) {
            load_stage(sb + ps * STAGE_BYTES + aSmBase,
                       sb + ps * STAGE_BYTES + bSmBase, ag, bg);
            ag += BKB;
            bg += BKB;
        }
        cp_commit();
        if (++ps == STAGES) ps = 0;
        cp_wait<STAGES - 2>();         // own G(ck+1) complete
        __syncthreads();               // 2: ALL threads' G(ck+1) complete

        uint32_t As = sb + cs * STAGE_BYTES;
        int cs1 = cs + 1; if (cs1 == STAGES) cs1 = 0;
        uint32_t AsNext = sb + cs1 * STAGE_BYTES;
        cs = cs1;

        if (!primed) {
#pragma unroll
            for (int mi = 0; mi < 4; mi++)
                ldmatrix4(a[0][mi][0], a[0][mi][1], a[0][mi][2], a[0][mi][3],
                          As + aOff[mi]);
#pragma unroll
            for (int np = 0; np < 4; np++)
                ldmatrix4(b[0][2 * np][0], b[0][2 * np][1],
                          b[0][2 * np + 1][0], b[0][2 * np + 1][1],
                          As + bOff[np]);
            primed = true;
        }

#pragma unroll
        for (int ks = 0; ks < 4; ks++) {
            int cur = ks & 1;
            int nxt = cur ^ 1;
            if (ks < 3) {
                uint32_t x = (uint32_t)((ks + 1) << 5);
#pragma unroll
                for (int mi = 0; mi < 4; mi++)
                    ldmatrix4(a[nxt][mi][0], a[nxt][mi][1], a[nxt][mi][2], a[nxt][mi][3],
                              (As + aOff[mi]) ^ x);
#pragma unroll
                for (int np = 0; np < 4; np++)
                    ldmatrix4(b[nxt][2 * np][0], b[nxt][2 * np][1],
                              b[nxt][2 * np + 1][0], b[nxt][2 * np + 1][1],
                              (As + bOff[np]) ^ x);
            } else if (ck + 1 < KCHUNKS) {
#pragma unroll
                for (int mi = 0; mi < 4; mi++)
                    ldmatrix4(a[nxt][mi][0], a[nxt][mi][1], a[nxt][mi][2], a[nxt][mi][3],
                              AsNext + aOff[mi]);
#pragma unroll
                for (int np = 0; np < 4; np++)
                    ldmatrix4(b[nxt][2 * np][0], b[nxt][2 * np][1],
                              b[nxt][2 * np + 1][0], b[nxt][2 * np + 1][1],
                              AsNext + bOff[np]);
            }
#pragma unroll
            for (int mi = 0; mi < 4; mi++)
#pragma unroll
                for (int ni = 0; ni < 8; ni++)
                    mma_bf16(acc[mi][ni][0], acc[mi][ni][1], acc[mi][ni][2], acc[mi][ni][3],
                             a[cur][mi][0], a[cur][mi][1], a[cur][mi][2], a[cur][mi][3],
                             b[cur][ni][0], b[cur][ni][1]);
        }
    }

    // Epilogue: out = acc*4 + bias
    int qrow = lid >> 2;
    int qcol = (lid & 3) * 2;
    int m0 = tm * BM + wm * 64 + qrow;
    int n0 = tn * BN + wn * 64 + qcol;
#pragma unroll
    for (int mi = 0; mi < 4; mi++) {
#pragma unroll
        for (int ni = 0; ni < 8; ni++) {
            int n = n0 + ni * 8;
            float b0 = __ldg(bias + n);
            float b1 = __ldg(bias + n + 1);
            int mA = m0 + mi * 16;
            int mB = mA + 8;
            float2 v0 = make_float2(acc[mi][ni][0] * 4.0f + b0,
                                    acc[mi][ni][1] * 4.0f + b1);
            float2 v1 = make_float2(acc[mi][ni][2] * 4.0f + b0,
                                    acc[mi][ni][3] * 4.0f + b1);
            *reinterpret_cast<float2*>(out + (size_t)mA * NDIM + n) = v0;
            *reinterpret_cast<float2*>(out + (size_t)mB * NDIM + n) = v1;
        }
    }
}

// ============================================================================
// Host launch
// ============================================================================
extern "C" void kernel_launch(void* const* d_in, const int* in_sizes, int n_in,
                              void* d_out, int out_size) {
    const float* input = nullptr;
    const void*  weight = nullptr;
    const float* bias = nullptr;
    for (int i = 0; i < n_in; i++) {
        if (in_sizes[i] == 4 * 4096 * 4096)  input = (const float*)d_in[i];
        else if (in_sizes[i] == 4096 * 4096) weight = d_in[i];
        else if (in_sizes[i] == 4096)        bias = (const float*)d_in[i];
    }
    if (!input)  input  = (const float*)d_in[0];
    if (!weight) weight = d_in[1];
    if (!bias)   bias   = (const float*)d_in[2];
    float* out = (float*)d_out;

    int n4 = (4 * 4096 * 4096) / 4;
    quant_act<<<8192, 256>>>((const float4*)input, n4);

    prep_w<<<2048, 256>>>(weight, 4096 * 4096);

    static bool attr_set = false;
    if (!attr_set) {
        cudaFuncSetAttribute(gemm_kernel,
                             cudaFuncAttributeMaxDynamicSharedMemorySize, SM_TOTAL);
        attr_set = true;
    }
    dim3 grid(NDIM / BN, MDIM / BM);   // (32, 128)
    gemm_kernel<<<grid, NTHREADS, SM_TOTAL>>>(bias, out);
}

// round 16
// speedup vs baseline: 1.0576x; 1.0085x over previous
#include <cuda_runtime.h>
#include <cuda_fp8.h>
#include <cuda_bf16.h>
#include <cstdint>

// ============================================================================
// y[b,s,o] = 4 * sum_i e4m3(x[b,s,i]*0.5) * W_e4m3[o,i]  + bias[o]
// M = 16384, N = 4096, K = 4096, fp32 out.
// R16: R15 GEMM (best) + fused prep:
//   - ONE prep kernel: blocks [0,8192) quantize activations (16B-vectorized),
//     blocks [8192,10240) convert weights (inline dtype detect). Both are
//     DRAM-bound; co-running saturates HBM instead of serializing.
//   - The *4 output scale is folded into the A operand (4*e4m3 exact in bf16),
//     so the GEMM epilogue is acc + bias.
// ============================================================================

#define DI __device__ __forceinline__

// ---------------- device scratch (bytes; bf16 payload) ----------------------
__device__ uint8_t g_Aq[16384u * 4096u * 2u];   // 128MB activations bf16 (4*e4m3)
__device__ uint8_t g_Wq[4096u * 4096u * 2u];    // 32MB weights bf16

// ---------------- helpers ---------------------------------------------------
DI uint32_t smem_u32(const void* p) {
    uint32_t a;
    asm("{ .reg .u64 t; cvta.to.shared.u64 t, %1; cvt.u32.u64 %0, t; }"
        : "=r"(a) : "l"(p));
    return a;
}
DI void cp_async16(uint32_t dst, const void* src) {
    asm volatile("cp.async.cg.shared.global [%0], [%1], 16;" :: "r"(dst), "l"(src));
}
DI void cp_commit() { asm volatile("cp.async.commit_group;" ::: "memory"); }
template <int N> DI void cp_wait() {
    asm volatile("cp.async.wait_group %0;" :: "n"(N) : "memory");
}
DI void ldmatrix4(uint32_t& r0, uint32_t& r1, uint32_t& r2, uint32_t& r3, uint32_t a) {
    asm volatile("ldmatrix.sync.aligned.m8n8.x4.shared.b16 {%0,%1,%2,%3}, [%4];"
                 : "=r"(r0), "=r"(r1), "=r"(r2), "=r"(r3) : "r"(a));
}
DI void mma_bf16(float& c0, float& c1, float& c2, float& c3,
                 uint32_t a0, uint32_t a1, uint32_t a2, uint32_t a3,
                 uint32_t b0, uint32_t b1) {
    asm volatile(
        "mma.sync.aligned.m16n8k16.row.col.f32.bf16.bf16.f32 "
        "{%0,%1,%2,%3}, {%4,%5,%6,%7}, {%8,%9}, {%0,%1,%2,%3};"
        : "+f"(c0), "+f"(c1), "+f"(c2), "+f"(c3)
        : "r"(a0), "r"(a1), "r"(a2), "r"(a3), "r"(b0), "r"(b1));
}

// e4m3 quantize (x*0.5, satfinite), widen (exact), fold *4 (exact), to bf16
DI __nv_bfloat16 qdq4_bf16(float x) {
    __nv_fp8_storage_t q = __nv_cvt_float_to_fp8(x * 0.5f, __NV_SATFINITE, __NV_E4M3);
    float f = __half2float(__nv_cvt_fp8_to_halfraw(q, __NV_E4M3));
    return __float2bfloat16(4.0f * f);
}
DI __nv_bfloat16 e4m3_bf16(uint8_t b) {
    float f = __half2float(__nv_cvt_fp8_to_halfraw((__nv_fp8_storage_t)b, __NV_E4M3));
    return __float2bfloat16(f);
}
DI uint32_t pack2(__nv_bfloat16 lo, __nv_bfloat16 hi) {
    __nv_bfloat162 p(lo, hi);
    return *reinterpret_cast<uint32_t*>(&p);
}

// ============================================================================
// Fused prep kernel: [0,QBLK) activations, [QBLK,QBLK+WBLK) weights.
// ============================================================================
#define QBLK 8192
#define WBLK 2048
#define PTHREADS 256

__global__ void prep_all(const float4* __restrict__ act,
                         const void* __restrict__ w) {
    if (blockIdx.x < QBLK) {
        // --- activations: 2x float4 in -> uint4 (8 bf16) out ---
        uint4* out = reinterpret_cast<uint4*>(g_Aq);
        int total = (16384 * 4096) / 8;           // uint4 outputs
        int i = blockIdx.x * PTHREADS + threadIdx.x;
        int stride = QBLK * PTHREADS;
        for (; i < total; i += stride) {
            float4 v0 = act[2 * i];
            float4 v1 = act[2 * i + 1];
            uint4 o;
            o.x = pack2(qdq4_bf16(v0.x), qdq4_bf16(v0.y));
            o.y = pack2(qdq4_bf16(v0.z), qdq4_bf16(v0.w));
            o.z = pack2(qdq4_bf16(v1.x), qdq4_bf16(v1.y));
            o.w = pack2(qdq4_bf16(v1.z), qdq4_bf16(v1.w));
            out[i] = o;
        }
    } else {
        // --- weights: inline dtype detect (first 256 floats), then convert ---
        const float* wf32 = (const float*)w;
        int t = threadIdx.x;
        int pred = (fabsf(wf32[t]) <= 448.0f) ? 1 : 0;   // NaN/Inf -> 0
        int cnt = __syncthreads_count(pred);
        int flag = (cnt == PTHREADS);                    // all pass => fp32

        int total = (4096 * 4096) / 8;                   // uint4 outputs
        int i = (blockIdx.x - QBLK) * PTHREADS + t;
        int stride = WBLK * PTHREADS;
        uint4* o = reinterpret_cast<uint4*>(g_Wq);
        if (flag) {
            const float4* wf = (const float4*)w;
            for (; i < total; i += stride) {
                float4 v0 = wf[2 * i];
                float4 v1 = wf[2 * i + 1];
                uint4 u;
                u.x = pack2(e4m3_bf16(__nv_cvt_float_to_fp8(v0.x, __NV_SATFINITE, __NV_E4M3)),
                            e4m3_bf16(__nv_cvt_float_to_fp8(v0.y, __NV_SATFINITE, __NV_E4M3)));
                u.y = pack2(e4m3_bf16(__nv_cvt_float_to_fp8(v0.z, __NV_SATFINITE, __NV_E4M3)),
                            e4m3_bf16(__nv_cvt_float_to_fp8(v0.w, __NV_SATFINITE, __NV_E4M3)));
                u.z = pack2(e4m3_bf16(__nv_cvt_float_to_fp8(v1.x, __NV_SATFINITE, __NV_E4M3)),
                            e4m3_bf16(__nv_cvt_float_to_fp8(v1.y, __NV_SATFINITE, __NV_E4M3)));
                u.w = pack2(e4m3_bf16(__nv_cvt_float_to_fp8(v1.z, __NV_SATFINITE, __NV_E4M3)),
                            e4m3_bf16(__nv_cvt_float_to_fp8(v1.w, __NV_SATFINITE, __NV_E4M3)));
                o[i] = u;
            }
        } else {
            const uint2* wb = (const uint2*)w;           // 8 e4m3 bytes
            for (; i < total; i += stride) {
                uint2 v = wb[i];
                uint4 u;
                u.x = pack2(e4m3_bf16((uint8_t)(v.x)),
                            e4m3_bf16((uint8_t)(v.x >> 8)));
                u.y = pack2(e4m3_bf16((uint8_t)(v.x >> 16)),
                            e4m3_bf16((uint8_t)(v.x >> 24)));
                u.z = pack2(e4m3_bf16((uint8_t)(v.y)),
                            e4m3_bf16((uint8_t)(v.y >> 8)));
                u.w = pack2(e4m3_bf16((uint8_t)(v.y >> 16)),
                            e4m3_bf16((uint8_t)(v.y >> 24)));
                o[i] = u;
            }
        }
    }
}

// ============================================================================
// GEMM (unchanged R15 mainloop; epilogue = acc + bias)
// ============================================================================
#define BM 128
#define BN 128
#define KBYTES 8192
#define BKB 128
#define NDIM 4096
#define MDIM 16384
#define KCHUNKS 64
#define STAGES 3
#define NTHREADS 128

#define A_BYTES (BM * 128)
#define B_BYTES (BN * 128)
#define STAGE_BYTES (A_BYTES + B_BYTES)
#define SM_TOTAL (STAGES * STAGE_BYTES)

DI void load_stage(uint32_t As, uint32_t Bs,
                   const uint8_t* __restrict__ ag,
                   const uint8_t* __restrict__ bg) {
#pragma unroll
    for (int i = 0; i < BM / 16; i++)
        cp_async16(As + i * (16 * 128), ag + (size_t)i * (16 * KBYTES));
#pragma unroll
    for (int i = 0; i < BN / 16; i++)
        cp_async16(Bs + i * (16 * 128), bg + (size_t)i * (16 * KBYTES));
}

__global__ void __launch_bounds__(NTHREADS, 2)
gemm_kernel(const float* __restrict__ bias, float* __restrict__ out) {
    extern __shared__ char smem[];
    uint32_t sb = smem_u32(smem);
    int tid = (int)threadIdx.x;
    int wid = tid >> 5;
    int lid = tid & 31;
    int wm = wid & 1;
    int wn = wid >> 1;
    int tm = blockIdx.y;
    int tn = blockIdx.x;

    int lcol = tid & 7;
    int lrow = tid >> 3;
    uint32_t aSmBase = (uint32_t)(lrow * 128 + ((lcol ^ (lrow & 7)) << 4));
    uint32_t bSmBase = aSmBase + A_BYTES;
    const uint8_t* ag = g_Aq + ((size_t)(tm * BM + lrow)) * KBYTES + lcol * 16;
    const uint8_t* bg = g_Wq + ((size_t)(tn * BN + lrow)) * KBYTES + lcol * 16;

    float acc[4][8][4];
#pragma unroll
    for (int mi = 0; mi < 4; mi++)
#pragma unroll
        for (int ni = 0; ni < 8; ni++)
#pragma unroll
            for (int r = 0; r < 4; r++) acc[mi][ni][r] = 0.0f;

    int a_row_l = (lid & 7) + ((lid >> 3) & 1) * 8;
    int a_half  = lid >> 4;
    int b_row_l = (lid & 7) + ((lid >> 4) & 1) * 8;
    int b_half  = (lid >> 3) & 1;

    uint32_t aOff[4], bOff[4];
#pragma unroll
    for (int mi = 0; mi < 4; mi++) {
        int row = wm * 64 + mi * 16 + a_row_l;
        aOff[mi] = (uint32_t)(row * 128 + ((a_half ^ (row & 7)) << 4));
    }
#pragma unroll
    for (int np = 0; np < 4; np++) {
        int n = wn * 64 + np * 16 + b_row_l;
        bOff[np] = (uint32_t)(n * 128 + ((b_half ^ (n & 7)) << 4)) + A_BYTES;
    }

#pragma unroll
    for (int s = 0; s < STAGES - 1; s++) {
        load_stage(sb + s * STAGE_BYTES + aSmBase, sb + s * STAGE_BYTES + bSmBase,
                   ag, bg);
        cp_commit();
        ag += BKB;
        bg += BKB;
    }

    uint32_t a[2][4][4];
    uint32_t b[2][8][2];
    int cs = 0;
    int ps = STAGES - 1;
    bool primed = false;

    for (int ck = 0; ck < KCHUNKS; ck++) {
        __syncthreads();               // 1: all reads of stage ps done
        if (ck + STAGES - 1 < KCHUNKS) {
            load_stage(sb + ps * STAGE_BYTES + aSmBase,
                       sb + ps * STAGE_BYTES + bSmBase, ag, bg);
            ag += BKB;
            bg += BKB;
        }
        cp_commit();
        if (++ps == STAGES) ps = 0;
        cp_wait<STAGES - 2>();         // own G(ck+1) complete
        __syncthreads();               // 2: ALL threads' G(ck+1) complete

        uint32_t As = sb + cs * STAGE_BYTES;
        int cs1 = cs + 1; if (cs1 == STAGES) cs1 = 0;
        uint32_t AsNext = sb + cs1 * STAGE_BYTES;
        cs = cs1;

        if (!primed) {
#pragma unroll
            for (int mi = 0; mi < 4; mi++)
                ldmatrix4(a[0][mi][0], a[0][mi][1], a[0][mi][2], a[0][mi][3],
                          As + aOff[mi]);
#pragma unroll
            for (int np = 0; np < 4; np++)
                ldmatrix4(b[0][2 * np][0], b[0][2 * np][1],
                          b[0][2 * np + 1][0], b[0][2 * np + 1][1],
                          As + bOff[np]);
            primed = true;
        }

#pragma unroll
        for (int ks = 0; ks < 4; ks++) {
            int cur = ks & 1;
            int nxt = cur ^ 1;
            if (ks < 3) {
                uint32_t x = (uint32_t)((ks + 1) << 5);
#pragma unroll
                for (int mi = 0; mi < 4; mi++)
                    ldmatrix4(a[nxt][mi][0], a[nxt][mi][1], a[nxt][mi][2], a[nxt][mi][3],
                              (As + aOff[mi]) ^ x);
#pragma unroll
                for (int np = 0; np < 4; np++)
                    ldmatrix4(b[nxt][2 * np][0], b[nxt][2 * np][1],
                              b[nxt][2 * np + 1][0], b[nxt][2 * np + 1][1],
                              (As + bOff[np]) ^ x);
            } else if (ck + 1 < KCHUNKS) {
#pragma unroll
                for (int mi = 0; mi < 4; mi++)
                    ldmatrix4(a[nxt][mi][0], a[nxt][mi][1], a[nxt][mi][2], a[nxt][mi][3],
                              AsNext + aOff[mi]);
#pragma unroll
                for (int np = 0; np < 4; np++)
                    ldmatrix4(b[nxt][2 * np][0], b[nxt][2 * np][1],
                              b[nxt][2 * np + 1][0], b[nxt][2 * np + 1][1],
                              AsNext + bOff[np]);
            }
#pragma unroll
            for (int mi = 0; mi < 4; mi++)
#pragma unroll
                for (int ni = 0; ni < 8; ni++)
                    mma_bf16(acc[mi][ni][0], acc[mi][ni][1], acc[mi][ni][2], acc[mi][ni][3],
                             a[cur][mi][0], a[cur][mi][1], a[cur][mi][2], a[cur][mi][3],
                             b[cur][ni][0], b[cur][ni][1]);
        }
    }

    // Epilogue: out = acc + bias (scale folded into A)
    int qrow = lid >> 2;
    int qcol = (lid & 3) * 2;
    int m0 = tm * BM + wm * 64 + qrow;
    int n0 = tn * BN + wn * 64 + qcol;
#pragma unroll
    for (int mi = 0; mi < 4; mi++) {
#pragma unroll
        for (int ni = 0; ni < 8; ni++) {
            int n = n0 + ni * 8;
            float b0 = __ldg(bias + n);
            float b1 = __ldg(bias + n + 1);
            int mA = m0 + mi * 16;
            int mB = mA + 8;
            float2 v0 = make_float2(acc[mi][ni][0] + b0, acc[mi][ni][1] + b1);
            float2 v1 = make_float2(acc[mi][ni][2] + b0, acc[mi][ni][3] + b1);
            *reinterpret_cast<float2*>(out + (size_t)mA * NDIM + n) = v0;
            *reinterpret_cast<float2*>(out + (size_t)mB * NDIM + n) = v1;
        }
    }
}

// ============================================================================
// Host launch
// ============================================================================
extern "C" void kernel_launch(void* const* d_in, const int* in_sizes, int n_in,
                              void* d_out, int out_size) {
    const float* input = nullptr;
    const void*  weight = nullptr;
    const float* bias = nullptr;
    for (int i = 0; i < n_in; i++) {
        if (in_sizes[i] == 4 * 4096 * 4096)  input = (const float*)d_in[i];
        else if (in_sizes[i] == 4096 * 4096) weight = d_in[i];
        else if (in_sizes[i] == 4096)        bias = (const float*)d_in[i];
    }
    if (!input)  input  = (const float*)d_in[0];
    if (!weight) weight = d_in[1];
    if (!bias)   bias   = (const float*)d_in[2];
    float* out = (float*)d_out;

    prep_all<<<QBLK + WBLK, PTHREADS>>>((const float4*)input, weight);

    static bool attr_set = false;
    if (!attr_set) {
        cudaFuncSetAttribute(gemm_kernel,
                             cudaFuncAttributeMaxDynamicSharedMemorySize, SM_TOTAL);
        attr_set = true;
    }
    dim3 grid(NDIM / BN, MDIM / BM);   // (32, 128)
    gemm_kernel<<<grid, NTHREADS, SM_TOTAL>>>(bias, out);
}